// round 6
// baseline (speedup 1.0000x reference)
#include <cuda_runtime.h>
#include <cuda_bf16.h>

// CRF loss: scaled linear-domain forward scan + gold score, fused.
// 1 warp per block handles TWO batch elements (interleaved recurrences for ILP).
// Each lane holds the FULL q vector (16 packed f32x2 regs) per batch plus a
// shared packed exp-transition row. Per step: 16 fma.rn.f32x2 matvec (zero
// shuffles), broadcast via ping-pong smem (1 STS + 3-cyc BAR + 8 LDS.128).
// Entire inner body is branch-free (SELP/FMAF for masking, unconditional
// exact power-of-2 rescale at compile-time-unrolled positions).

#define BB 256
#define LL 2048
#define TT 32
#define START_IDX 0
#define STOP_IDX 1

typedef unsigned long long u64;

__device__ float g_partial[BB];

__device__ __forceinline__ u64 ffma2(u64 a, u64 b, u64 c) {
    u64 d; asm("fma.rn.f32x2 %0, %1, %2, %3;" : "=l"(d) : "l"(a), "l"(b), "l"(c)); return d;
}
__device__ __forceinline__ u64 fadd2(u64 a, u64 b) {
    u64 d; asm("add.rn.f32x2 %0, %1, %2;" : "=l"(d) : "l"(a), "l"(b)); return d;
}
__device__ __forceinline__ u64 fmul2(u64 a, u64 b) {
    u64 d; asm("mul.rn.f32x2 %0, %1, %2;" : "=l"(d) : "l"(a), "l"(b)); return d;
}
__device__ __forceinline__ u64 pack2(float lo, float hi) {
    return ((u64)__float_as_uint(hi) << 32) | (u64)__float_as_uint(lo);
}
__device__ __forceinline__ float lo2(u64 v) { return __uint_as_float((unsigned)v); }
__device__ __forceinline__ float hi2(u64 v) { return __uint_as_float((unsigned)(v >> 32)); }

// per-batch persistent state
struct Lane {
    u64   qp[16];     // full q vector (packed pairs), identical across lanes
    float qcur;       // this lane's own q element (= q[lane])
    long long off_e;  // exact power-of-2 scale offset (exponent units)
    float gtrans, gemit;
    int   prev, last;
};

__global__ void __launch_bounds__(32) crf_fwd_kernel(
    const float* __restrict__ efeats,
    const float* __restrict__ mask,
    const int*   __restrict__ tgt,
    const float* __restrict__ transitions)
{
    __shared__ __align__(16) float sq[2][2][TT];  // [pingpong][batch][tag]
    __shared__ float tr[TT * TT];
    const int lane = threadIdx.x;
    const int bA = 2 * blockIdx.x;
    const int bB = bA + 1;

    #pragma unroll
    for (int i = lane; i < TT * TT; i += 32) tr[i] = transitions[i];
    __syncthreads();

    // shared packed E row for this lane's 'next' tag
    u64 Erp[16];
    #pragma unroll
    for (int j = 0; j < 16; j++)
        Erp[j] = pack2(__expf(tr[lane * TT + 2 * j]), __expf(tr[lane * TT + 2 * j + 1]));

    Lane A, B;
    #pragma unroll
    for (int j = 0; j < 16; j++) { A.qp[j] = 0ull; B.qp[j] = 0ull; }
    A.qp[0] = pack2(1.0f, 0.0f);  B.qp[0] = pack2(1.0f, 0.0f);   // START_IDX == 0
    A.qcur = (lane == START_IDX) ? 1.0f : 0.0f;  B.qcur = A.qcur;
    A.off_e = 0;  B.off_e = 0;
    A.gtrans = A.gemit = 0.0f;  B.gtrans = B.gemit = 0.0f;
    A.prev = A.last = START_IDX;  B.prev = B.last = START_IDX;

    const float* fbA = efeats + (size_t)bA * LL * TT;
    const float* fbB = efeats + (size_t)bB * LL * TT;
    const float* mbA = mask + (size_t)bA * LL;
    const float* mbB = mask + (size_t)bB * LL;
    const int*   tbA = tgt  + (size_t)bA * LL;
    const int*   tbB = tgt  + (size_t)bB * LL;

    int buf = 0;

    for (int l0 = 0; l0 < LL; l0 += 4) {
        // ---- prefetch 4 steps for both batches ----
        float fA[4], fB[4], eA[4], eB[4];
        #pragma unroll
        for (int i = 0; i < 4; i++) { fA[i] = fbA[(l0 + i) * TT + lane];
                                      fB[i] = fbB[(l0 + i) * TT + lane]; }
        #pragma unroll
        for (int i = 0; i < 4; i++) { eA[i] = __expf(fA[i]); eB[i] = __expf(fB[i]); }
        float4 m4A = *(const float4*)(mbA + l0);
        float4 m4B = *(const float4*)(mbB + l0);
        int4   t4A = *(const int4*)(tbA + l0);
        int4   t4B = *(const int4*)(tbB + l0);
        float mkA[4] = {m4A.x, m4A.y, m4A.z, m4A.w};
        float mkB[4] = {m4B.x, m4B.y, m4B.z, m4B.w};
        int   tgA[4] = {t4A.x, t4A.y, t4A.z, t4A.w};
        int   tgB[4] = {t4B.x, t4B.y, t4B.z, t4B.w};

        #pragma unroll
        for (int i = 0; i < 4; i++) {
            // ---- matvecs (independent A/B chains, compiler interleaves) ----
            u64 a0 = 0ull, a1 = 0ull, a2 = 0ull, a3 = 0ull;
            u64 b0 = 0ull, b1 = 0ull, b2 = 0ull, b3 = 0ull;
            #pragma unroll
            for (int j = 0; j < 16; j += 4) {
                a0 = ffma2(A.qp[j + 0], Erp[j + 0], a0);
                b0 = ffma2(B.qp[j + 0], Erp[j + 0], b0);
                a1 = ffma2(A.qp[j + 1], Erp[j + 1], a1);
                b1 = ffma2(B.qp[j + 1], Erp[j + 1], b1);
                a2 = ffma2(A.qp[j + 2], Erp[j + 2], a2);
                b2 = ffma2(B.qp[j + 2], Erp[j + 2], b2);
                a3 = ffma2(A.qp[j + 3], Erp[j + 3], a3);
                b3 = ffma2(B.qp[j + 3], Erp[j + 3], b3);
            }
            u64 sA = fadd2(fadd2(a0, a1), fadd2(a2, a3));
            u64 sB = fadd2(fadd2(b0, b1), fadd2(b2, b3));
            float qnA = eA[i] * (lo2(sA) + hi2(sA));
            float qnB = eB[i] * (lo2(sB) + hi2(sB));

            // ---- branch-free mask select + gold terms ----
            const bool onA = mkA[i] > 0.0f;  const bool onB = mkB[i] > 0.0f;
            const float ofA = onA ? 1.0f : 0.0f;
            const float ofB = onB ? 1.0f : 0.0f;
            const int tagA = tgA[i], tagB = tgB[i];
            A.qcur = onA ? qnA : A.qcur;
            B.qcur = onB ? qnB : B.qcur;
            A.gtrans = fmaf(ofA, tr[tagA * TT + A.prev], A.gtrans);
            B.gtrans = fmaf(ofB, tr[tagB * TT + B.prev], B.gtrans);
            A.gemit = fmaf((lane == tagA) ? ofA : 0.0f, fA[i], A.gemit);
            B.gemit = fmaf((lane == tagB) ? ofB : 0.0f, fB[i], B.gemit);
            A.last = onA ? tagA : A.last;
            B.last = onB ? tagB : B.last;
            A.prev = tagA;  B.prev = tagB;

            // ---- broadcast: 2 STS + one 3-cycle BAR + 16 LDS.128 ----
            sq[buf][0][lane] = A.qcur;
            sq[buf][1][lane] = B.qcur;
            __syncthreads();
            const ulonglong2* pA = (const ulonglong2*)sq[buf][0];
            const ulonglong2* pB = (const ulonglong2*)sq[buf][1];
            #pragma unroll
            for (int j = 0; j < 8; j++) {
                ulonglong2 vA = pA[j];  ulonglong2 vB = pB[j];
                A.qp[2 * j] = vA.x;  A.qp[2 * j + 1] = vA.y;
                B.qp[2 * j] = vB.x;  B.qp[2 * j + 1] = vB.y;
            }
            buf ^= 1;

            // ---- exact power-of-2 rescale every 4 steps (compile-time i, no branch) ----
            if (i == 3) {
                int eEA = (int)(((unsigned)A.qp[0] >> 23) & 0xff);
                int eEB = (int)(((unsigned)B.qp[0] >> 23) & 0xff);
                float scA = __int_as_float((unsigned)(254 - eEA) << 23);  // 2^(127-e)
                float scB = __int_as_float((unsigned)(254 - eEB) << 23);
                u64 sc2A = pack2(scA, scA);  u64 sc2B = pack2(scB, scB);
                #pragma unroll
                for (int j = 0; j < 16; j++) {
                    A.qp[j] = fmul2(A.qp[j], sc2A);
                    B.qp[j] = fmul2(B.qp[j], sc2B);
                }
                A.qcur *= scA;  B.qcur *= scB;
                A.off_e += (long long)(eEA - 127);
                B.off_e += (long long)(eEB - 127);
            }
        }
    }

    // ---- terminal logsumexp (redundant per-lane, no reduction needed) ----
    float tA = 0.0f, tB = 0.0f;
    #pragma unroll
    for (int j = 0; j < 16; j++) {
        float e0 = __expf(tr[STOP_IDX * TT + 2 * j]);
        float e1 = __expf(tr[STOP_IDX * TT + 2 * j + 1]);
        tA += lo2(A.qp[j]) * e0;  tA += hi2(A.qp[j]) * e1;
        tB += lo2(B.qp[j]) * e0;  tB += hi2(B.qp[j]) * e1;
    }

    // only the emit terms are lane-distributed — one final warp reduction each
    #pragma unroll
    for (int o = 16; o; o >>= 1) {
        A.gemit += __shfl_xor_sync(0xffffffffu, A.gemit, o);
        B.gemit += __shfl_xor_sync(0xffffffffu, B.gemit, o);
    }

    if (lane == 0) {
        double fwdA = (double)A.off_e * 0.6931471805599453 + (double)logf(tA);
        double fwdB = (double)B.off_e * 0.6931471805599453 + (double)logf(tB);
        double goldA = (double)A.gtrans + (double)A.gemit + (double)tr[STOP_IDX * TT + A.last];
        double goldB = (double)B.gtrans + (double)B.gemit + (double)tr[STOP_IDX * TT + B.last];
        g_partial[bA] = (float)(fwdA - goldA);
        g_partial[bB] = (float)(fwdB - goldB);
    }
}

__global__ void crf_reduce_kernel(float* __restrict__ out)
{
    const int tid = threadIdx.x;   // 256 threads
    __shared__ float s[8];
    float v = g_partial[tid];
    #pragma unroll
    for (int o = 16; o; o >>= 1) v += __shfl_xor_sync(0xffffffffu, v, o);
    if ((tid & 31) == 0) s[tid >> 5] = v;
    __syncthreads();
    if (tid < 32) {
        float x = (tid < 8) ? s[tid] : 0.0f;
        #pragma unroll
        for (int o = 4; o; o >>= 1) x += __shfl_xor_sync(0xffffffffu, x, o);
        if (tid == 0) *out = x / (float)BB;
    }
}

extern "C" void kernel_launch(void* const* d_in, const int* in_sizes, int n_in,
                              void* d_out, int out_size)
{
    const float* efeats      = (const float*)d_in[0];
    const float* mask        = (const float*)d_in[1];
    const int*   tgt         = (const int*)  d_in[2];
    const float* transitions = (const float*)d_in[3];
    float* out = (float*)d_out;

    crf_fwd_kernel<<<BB / 2, 32>>>(efeats, mask, tgt, transitions);
    crf_reduce_kernel<<<1, BB>>>(out);
}

// round 7
// speedup vs baseline: 1.7062x; 1.7062x over previous
#include <cuda_runtime.h>
#include <cuda_bf16.h>

// CRF loss: scaled linear-domain forward scan + gold score, fused.
// 1 warp (=1 block, BAR.SYNC floor 3cyc) per batch element; lane = tag.
// Each lane holds the FULL q vector (16 packed f32x2 regs) + its packed
// exp-transition row: per-step matvec = 16 fma.rn.f32x2, zero shuffles.
// q broadcast via ping-pong smem: 1 STS + BAR + 8 broadcast LDS.128.
// Branch-free inner body (SELP/FMAF masking, compile-time rescale points).
// Double-buffered software prefetch: group g+1's LDGs issue before group g
// is processed, so DRAM latency never touches the recurrence.

#define BB 256
#define LL 2048
#define TT 32
#define START_IDX 0
#define STOP_IDX 1

typedef unsigned long long u64;

__device__ float g_partial[BB];

__device__ __forceinline__ u64 ffma2(u64 a, u64 b, u64 c) {
    u64 d; asm("fma.rn.f32x2 %0, %1, %2, %3;" : "=l"(d) : "l"(a), "l"(b), "l"(c)); return d;
}
__device__ __forceinline__ u64 fadd2(u64 a, u64 b) {
    u64 d; asm("add.rn.f32x2 %0, %1, %2;" : "=l"(d) : "l"(a), "l"(b)); return d;
}
__device__ __forceinline__ u64 fmul2(u64 a, u64 b) {
    u64 d; asm("mul.rn.f32x2 %0, %1, %2;" : "=l"(d) : "l"(a), "l"(b)); return d;
}
__device__ __forceinline__ u64 pack2(float lo, float hi) {
    return ((u64)__float_as_uint(hi) << 32) | (u64)__float_as_uint(lo);
}
__device__ __forceinline__ float lo2(u64 v) { return __uint_as_float((unsigned)v); }
__device__ __forceinline__ float hi2(u64 v) { return __uint_as_float((unsigned)(v >> 32)); }

// issue 8 steps of loads (no consumption here -> latency hidden)
#define LOADG(F, MA, MB4, TA, TB4, BASE) do {                                 \
    _Pragma("unroll")                                                         \
    for (int _i = 0; _i < 8; _i++)                                            \
        F[_i] = fb[(size_t)((BASE) + _i) * TT + lane];                        \
    MA  = *(const float4*)(mbp + (BASE));                                     \
    MB4 = *(const float4*)(mbp + (BASE) + 4);                                 \
    TA  = *(const int4*)(tbp + (BASE));                                       \
    TB4 = *(const int4*)(tbp + (BASE) + 4);                                   \
} while (0)

// process 8 steps from a prefetched buffer (fully branch-free)
#define PROC(F, MA, MB4, TA, TB4) do {                                        \
    float mk[8] = {MA.x, MA.y, MA.z, MA.w, MB4.x, MB4.y, MB4.z, MB4.w};       \
    int   tg[8] = {TA.x, TA.y, TA.z, TA.w, TB4.x, TB4.y, TB4.z, TB4.w};       \
    _Pragma("unroll")                                                         \
    for (int i = 0; i < 8; i++) {                                             \
        float ef = __expf(F[i]);         /* MUFU lat hidden under matvec */   \
        u64 a0 = 0ull, a1 = 0ull, a2 = 0ull, a3 = 0ull;                       \
        _Pragma("unroll")                                                     \
        for (int j = 0; j < 4; j++) a0 = ffma2(qp[j],      Erp[j],      a0);  \
        _Pragma("unroll")                                                     \
        for (int j = 0; j < 4; j++) a1 = ffma2(qp[j + 4],  Erp[j + 4],  a1);  \
        _Pragma("unroll")                                                     \
        for (int j = 0; j < 4; j++) a2 = ffma2(qp[j + 8],  Erp[j + 8],  a2);  \
        _Pragma("unroll")                                                     \
        for (int j = 0; j < 4; j++) a3 = ffma2(qp[j + 12], Erp[j + 12], a3);  \
        u64 s = fadd2(fadd2(a0, a1), fadd2(a2, a3));                          \
        float qn = ef * (lo2(s) + hi2(s));                                    \
        const bool  on = mk[i] > 0.0f;   /* warp-uniform */                   \
        const float of = on ? 1.0f : 0.0f;                                    \
        const int  tag = tg[i];                                               \
        qcur   = on ? qn : qcur;                                              \
        gtrans = fmaf(of, tr[tag * TT + prev], gtrans);                       \
        gemit  = fmaf((lane == tag) ? of : 0.0f, F[i], gemit);                \
        last   = on ? tag : last;                                             \
        prev   = tag;                                                         \
        sq[buf][lane] = qcur;                                                 \
        __syncthreads();                 /* 32-thr block: BAR floor ~3cyc */  \
        {                                                                     \
            const ulonglong2* p = (const ulonglong2*)sq[buf];                 \
            _Pragma("unroll")                                                 \
            for (int j = 0; j < 8; j++) {                                     \
                ulonglong2 v = p[j];                                          \
                qp[2 * j] = v.x;  qp[2 * j + 1] = v.y;                        \
            }                                                                 \
        }                                                                     \
        buf ^= 1;                                                             \
        if ((i & 3) == 3) {              /* exact power-of-2 rescale */       \
            int e = (int)(((unsigned)qp[0] >> 23) & 0xff);                    \
            float sc = __int_as_float((unsigned)(254 - e) << 23);             \
            u64 sc2 = pack2(sc, sc);                                          \
            _Pragma("unroll")                                                 \
            for (int j = 0; j < 16; j++) qp[j] = fmul2(qp[j], sc2);           \
            qcur *= sc;                                                       \
            off_e += (long long)(e - 127);                                    \
        }                                                                     \
    }                                                                         \
} while (0)

__global__ void __launch_bounds__(32) crf_fwd_kernel(
    const float* __restrict__ efeats,
    const float* __restrict__ mask,
    const int*   __restrict__ tgt,
    const float* __restrict__ transitions)
{
    __shared__ __align__(16) float sq[2][TT];   // ping-pong broadcast buffers
    __shared__ float tr[TT * TT];
    const int lane = threadIdx.x;
    const int b = blockIdx.x;

    #pragma unroll
    for (int i = lane; i < TT * TT; i += 32) tr[i] = transitions[i];
    __syncthreads();

    // packed E row for my 'next' tag: Erp[j] = (exp(tr[lane][2j]), exp(tr[lane][2j+1]))
    u64 Erp[16];
    #pragma unroll
    for (int j = 0; j < 16; j++)
        Erp[j] = pack2(__expf(tr[lane * TT + 2 * j]), __expf(tr[lane * TT + 2 * j + 1]));

    // full q vector per lane; init = unit vector at START_IDX(=0)
    u64 qp[16];
    #pragma unroll
    for (int j = 0; j < 16; j++) qp[j] = 0ull;
    qp[0] = pack2(1.0f, 0.0f);
    float qcur = (lane == START_IDX) ? 1.0f : 0.0f;

    const float* fb  = efeats + (size_t)b * LL * TT;
    const float* mbp = mask   + (size_t)b * LL;
    const int*   tbp = tgt    + (size_t)b * LL;

    long long off_e = 0;
    int   buf    = 0;
    int   prev   = START_IDX, last = START_IDX;
    float gtrans = 0.0f, gemit = 0.0f;

    // double-buffered state
    float  f0[8], f1[8];
    float4 m0a, m0b, m1a, m1b;
    int4   t0a, t0b, t1a, t1b;

    LOADG(f0, m0a, m0b, t0a, t0b, 0);           // prime buffer 0

    for (int l0 = 0; l0 < LL; l0 += 16) {
        LOADG(f1, m1a, m1b, t1a, t1b, l0 + 8);  // prefetch next group
        PROC (f0, m0a, m0b, t0a, t0b);
        const int ln = (l0 + 16 < LL) ? (l0 + 16) : l0;  // last iter: dummy reload
        LOADG(f0, m0a, m0b, t0a, t0b, ln);
        PROC (f1, m1a, m1b, t1a, t1b);
    }

    // terminal logsumexp — every lane holds the full q vector (no reduction)
    float t = 0.0f;
    #pragma unroll
    for (int j = 0; j < 16; j++) {
        t += lo2(qp[j]) * __expf(tr[STOP_IDX * TT + 2 * j]);
        t += hi2(qp[j]) * __expf(tr[STOP_IDX * TT + 2 * j + 1]);
    }

    // only the emit term is lane-distributed — one final warp reduction
    #pragma unroll
    for (int o = 16; o; o >>= 1) gemit += __shfl_xor_sync(0xffffffffu, gemit, o);

    if (lane == 0) {
        double fwd  = (double)off_e * 0.6931471805599453 + (double)logf(t);
        double gold = (double)gtrans + (double)gemit + (double)tr[STOP_IDX * TT + last];
        g_partial[b] = (float)(fwd - gold);
    }
}

__global__ void crf_reduce_kernel(float* __restrict__ out)
{
    const int tid = threadIdx.x;   // 256 threads
    __shared__ float s[8];
    float v = g_partial[tid];
    #pragma unroll
    for (int o = 16; o; o >>= 1) v += __shfl_xor_sync(0xffffffffu, v, o);
    if ((tid & 31) == 0) s[tid >> 5] = v;
    __syncthreads();
    if (tid < 32) {
        float x = (tid < 8) ? s[tid] : 0.0f;
        #pragma unroll
        for (int o = 4; o; o >>= 1) x += __shfl_xor_sync(0xffffffffu, x, o);
        if (tid == 0) *out = x / (float)BB;
    }
}

extern "C" void kernel_launch(void* const* d_in, const int* in_sizes, int n_in,
                              void* d_out, int out_size)
{
    const float* efeats      = (const float*)d_in[0];
    const float* mask        = (const float*)d_in[1];
    const int*   tgt         = (const int*)  d_in[2];
    const float* transitions = (const float*)d_in[3];
    float* out = (float*)d_out;

    crf_fwd_kernel<<<BB, 32>>>(efeats, mask, tgt, transitions);
    crf_reduce_kernel<<<1, BB>>>(out);
}